// round 14
// baseline (speedup 1.0000x reference)
#include <cuda_runtime.h>
#include <cstdint>

typedef unsigned long long u64;
typedef unsigned int u32;

#define HWDIM 224
#define HWPIX (HWDIM*HWDIM)   // 50176
#define NB    16
#define NTOK  49
#define CH    64
#define NOUT  80               // q(0..7) k(8..15) v(16..79)

// scratch: pixel-linear qkv [b][hw][80]
__device__ float g_qkv[(size_t)NB * HWPIX * NOUT];

__device__ __forceinline__ float tf32r(float f){
    u32 r;
    asm("cvt.rna.tf32.f32 %0, %1;" : "=r"(r) : "f"(f));
    return __uint_as_float(r);
}
__device__ __forceinline__ void mma_tf32(float* d, const u32* a, u32 b0, u32 b1){
    asm volatile(
        "mma.sync.aligned.m16n8k8.row.col.f32.tf32.tf32.f32 "
        "{%0,%1,%2,%3}, {%4,%5,%6,%7}, {%8,%9}, {%0,%1,%2,%3};"
        : "+f"(d[0]), "+f"(d[1]), "+f"(d[2]), "+f"(d[3])
        : "r"(a[0]), "r"(a[1]), "r"(a[2]), "r"(a[3]), "r"(b0), "r"(b1));
}

// ===================== K1: fused QKV projection (tf32 tensor cores) ===========
#define WCT_S 84
#define XT_S  67
#define OFF_XT   5376
#define OFF_BIAS 13952
#define OS1_S    84
#define K1_SMEM_FLOATS 14032
#define K1_SMEM_BYTES  (K1_SMEM_FLOATS*4)   // 56128

__global__ void __launch_bounds__(128, 4)
proj_kernel(const float* __restrict__ x,
            const float* __restrict__ Wq, const float* __restrict__ bq,
            const float* __restrict__ Wk, const float* __restrict__ bk,
            const float* __restrict__ Wv, const float* __restrict__ bv)
{
    extern __shared__ float s1[];
    const int tid = threadIdx.x;
    const int blk = blockIdx.x;               // 16 * 392
    const int b   = blk / 392;
    const int hw0 = (blk - b * 392) * 128;

    for (int idx = tid; idx < 512; idx += 128) {
        int o = idx >> 6, c = idx & 63;
        s1[c * WCT_S + o]     = tf32r(__ldg(&Wq[idx]));
        s1[c * WCT_S + 8 + o] = tf32r(__ldg(&Wk[idx]));
    }
    for (int idx = tid; idx < 4096; idx += 128) {
        int o = idx >> 6, c = idx & 63;
        s1[c * WCT_S + 16 + o] = tf32r(__ldg(&Wv[idx]));
    }
    if (tid < 80)
        s1[OFF_BIAS + tid] = (tid < 8)  ? __ldg(&bq[tid])
                           : (tid < 16) ? __ldg(&bk[tid - 8])
                                        : __ldg(&bv[tid - 16]);
    {
        const float* xb = x + (size_t)b * CH * HWPIX + hw0 + tid;
        float* xr = s1 + OFF_XT + tid * XT_S;
        #pragma unroll 8
        for (int c = 0; c < CH; c++)
            xr[c] = tf32r(__ldg(xb + (size_t)c * HWPIX));
    }
    __syncthreads();

    const int wid  = tid >> 5, lane = tid & 31;
    const int grp  = lane >> 2;
    const int tig  = lane & 3;
    const int pb   = wid * 32;

    float d[2][10][4];
    #pragma unroll
    for (int mt = 0; mt < 2; mt++)
        #pragma unroll
        for (int nt = 0; nt < 10; nt++)
            #pragma unroll
            for (int e = 0; e < 4; e++) d[mt][nt][e] = 0.0f;

    const u32* xtu = reinterpret_cast<const u32*>(s1 + OFF_XT);
    const u32* wcu = reinterpret_cast<const u32*>(s1);

    #pragma unroll
    for (int k0 = 0; k0 < 64; k0 += 8) {
        u32 a[2][4];
        #pragma unroll
        for (int mt = 0; mt < 2; mt++) {
            int base = pb + mt * 16;
            a[mt][0] = xtu[(base + grp)     * XT_S + k0 + tig];
            a[mt][1] = xtu[(base + grp + 8) * XT_S + k0 + tig];
            a[mt][2] = xtu[(base + grp)     * XT_S + k0 + tig + 4];
            a[mt][3] = xtu[(base + grp + 8) * XT_S + k0 + tig + 4];
        }
        #pragma unroll
        for (int nt = 0; nt < 10; nt++) {
            u32 b0 = wcu[(k0 + tig)     * WCT_S + nt * 8 + grp];
            u32 b1 = wcu[(k0 + tig + 4) * WCT_S + nt * 8 + grp];
            mma_tf32(d[0][nt], a[0], b0, b1);
            mma_tf32(d[1][nt], a[1], b0, b1);
        }
    }
    __syncthreads();

    const float* sb = s1 + OFF_BIAS;
    #pragma unroll
    for (int mt = 0; mt < 2; mt++) {
        int p0 = pb + mt * 16 + grp;
        #pragma unroll
        for (int nt = 0; nt < 10; nt++) {
            int n0 = nt * 8 + 2 * tig;
            float b0v = sb[n0], b1v = sb[n0 + 1];
            *reinterpret_cast<float2*>(s1 + p0 * OS1_S + n0)
                = make_float2(d[mt][nt][0] + b0v, d[mt][nt][1] + b1v);
            *reinterpret_cast<float2*>(s1 + (p0 + 8) * OS1_S + n0)
                = make_float2(d[mt][nt][2] + b0v, d[mt][nt][3] + b1v);
        }
    }
    __syncthreads();

    float4* dst = reinterpret_cast<float4*>(g_qkv + ((size_t)b * HWPIX + hw0) * NOUT);
    for (int i = tid; i < 2560; i += 128) {
        int p  = i / 20;
        int c4 = i - p * 20;
        dst[i] = *reinterpret_cast<const float4*>(s1 + p * OS1_S + c4 * 4);
    }
}

// ===================== K2: windowed attention (tf32, 4 windows / 256 thr) =====
#define QKV_S 84
#define AT_S 58
#define ATT_OFF 4116
#define OS_STRIDE 66
#define PW4 6964
#define K2_SMEM_FLOATS (4*PW4)              // 27856
#define K2_SMEM_BYTES  (K2_SMEM_FLOATS*4)   // 111424

__global__ void __launch_bounds__(256, 2)
attn_kernel(const float* __restrict__ x,
            const float* __restrict__ gamma,
            float* __restrict__ out)
{
    extern __shared__ float sp[];
    const int tid = threadIdx.x;
    const int blk = blockIdx.x;        // 16 b * 32 wh * 8 wquad
    const int b   = blk >> 8;
    const int rem = blk & 255;
    const int wh  = rem >> 3;
    const int wq  = rem & 7;
    const int h0  = wh * 7;
    const int w0  = wq * 28;

    const float g = __ldg(gamma);

    const int wid  = tid >> 5, lane = tid & 31;
    const int grp  = lane >> 2, tig = lane & 3;
    const int win  = wid >> 1;
    const int half = wid & 1;

    float* pool = sp + win * PW4;
    float* att  = pool + ATT_OFF;
    const u32* pu = reinterpret_cast<const u32*>(pool);

    // ---- stage qkv: 7 rows x 28 px x 80 floats (2240 contiguous each) ----
    const float* gq = g_qkv + ((size_t)b * HWPIX + (size_t)h0 * HWDIM + w0) * NOUT;
    for (int i = tid; i < 3920; i += 256) {
        int ph = i / 560;
        int rr = i - ph * 560;
        int pw = rr / 20;
        int c4 = rr - pw * 20;
        int wn = pw / 7;
        int t  = ph * 7 + (pw - wn * 7);
        float4 v = __ldg(reinterpret_cast<const float4*>(gq + ((size_t)ph * HWDIM + pw) * NOUT) + c4);
        *reinterpret_cast<float4*>(sp + wn * PW4 + t * QKV_S + c4 * 4) = v;
    }
    // zero att pad cols m = 49..55
    for (int i = tid; i < 1372; i += 256) {
        int wn = i / 343;
        int r  = i - wn * 343;
        int n  = r / 7, j = r - n * 7;
        sp[wn * PW4 + ATT_OFF + n * AT_S + 49 + j] = 0.0f;
    }
    __syncthreads();   // B1: all staging visible

    // ---- QK^T (rows warp-local) ----
    #pragma unroll
    for (int mt = 0; mt < 2; mt++) {
        int r0 = (half * 2 + mt) * 16 + grp;
        int r1 = r0 + 8;
        int r0c = min(r0, 48), r1c = min(r1, 48);
        u32 a[4];
        a[0] = pu[r0c * QKV_S + tig];
        a[1] = pu[r1c * QKV_S + tig];
        a[2] = pu[r0c * QKV_S + tig + 4];
        a[3] = pu[r1c * QKV_S + tig + 4];
        float dq[7][4];
        #pragma unroll
        for (int nt = 0; nt < 7; nt++)
            #pragma unroll
            for (int e = 0; e < 4; e++) dq[nt][e] = 0.0f;
        #pragma unroll
        for (int nt = 0; nt < 7; nt++) {
            int m = nt * 8 + grp;
            u32 b0 = 0, b1 = 0;
            if (m < NTOK) {
                b0 = pu[m * QKV_S + 8 + tig];
                b1 = pu[m * QKV_S + 8 + tig + 4];
            }
            mma_tf32(dq[nt], a, b0, b1);
        }
        #pragma unroll
        for (int nt = 0; nt < 7; nt++) {
            int c0 = nt * 8 + 2 * tig;
            if (r0 < NTOK) {
                if (c0 < NTOK)     att[r0 * AT_S + c0]     = dq[nt][0];
                if (c0 + 1 < NTOK) att[r0 * AT_S + c0 + 1] = dq[nt][1];
            }
            if (r1 < NTOK) {
                if (c0 < NTOK)     att[r1 * AT_S + c0]     = dq[nt][2];
                if (c0 + 1 < NTOK) att[r1 * AT_S + c0 + 1] = dq[nt][3];
            }
        }
    }
    __syncwarp();

    // ---- softmax (rows warp-local), gamma folded ----
    {
        int row = half * 32 + lane;
        if (row < NTOK) {
            float* ar = att + row * AT_S;
            float mx = ar[0];
            #pragma unroll 7
            for (int m = 1; m < NTOK; m++) mx = fmaxf(mx, ar[m]);
            float s = 0.0f;
            #pragma unroll 7
            for (int m = 0; m < NTOK; m++) {
                float e = __expf(ar[m] - mx);
                ar[m] = e;
                s += e;
            }
            float rs = g / s;
            #pragma unroll 7
            for (int m = 0; m < NTOK; m++) ar[m] = tf32r(ar[m] * rs);
        }
    }
    __syncwarp();

    // ---- AV ----
    float dv[2][8][4];
    #pragma unroll
    for (int mt = 0; mt < 2; mt++)
        #pragma unroll
        for (int nt = 0; nt < 8; nt++)
            #pragma unroll
            for (int e = 0; e < 4; e++) dv[mt][nt][e] = 0.0f;
    {
        const u32* au = reinterpret_cast<const u32*>(att);
        int r0 = (half * 2) * 16 + grp;
        int r0c = min(r0, 48),      r1c = min(r0 + 8, 48);
        int r2c = min(r0 + 16, 48), r3c = min(r0 + 24, 48);
        #pragma unroll
        for (int ks = 0; ks < 7; ks++) {
            int k0 = ks * 8;
            u32 a0[4], a1[4];
            a0[0] = au[r0c * AT_S + k0 + tig];
            a0[1] = au[r1c * AT_S + k0 + tig];
            a0[2] = au[r0c * AT_S + k0 + tig + 4];
            a0[3] = au[r1c * AT_S + k0 + tig + 4];
            a1[0] = au[r2c * AT_S + k0 + tig];
            a1[1] = au[r3c * AT_S + k0 + tig];
            a1[2] = au[r2c * AT_S + k0 + tig + 4];
            a1[3] = au[r3c * AT_S + k0 + tig + 4];
            #pragma unroll
            for (int nt = 0; nt < 8; nt++) {
                int c = nt * 8 + grp;
                u32 b0 = 0, b1 = 0;
                int m0 = k0 + tig;
                if (ks < 6) {
                    b0 = pu[m0 * QKV_S + 16 + c];
                    b1 = pu[(m0 + 4) * QKV_S + 16 + c];
                } else {
                    if (m0 < NTOK) b0 = pu[m0 * QKV_S + 16 + c];  // only m=48
                }
                mma_tf32(dv[0][nt], a0, b0, b1);
                mma_tf32(dv[1][nt], a1, b0, b1);
            }
        }
    }
    // per-window barrier (64 threads): qkv reads done before os overlays it
    asm volatile("bar.sync %0, 64;" :: "r"(1 + win) : "memory");

    // ---- epilogue: os[t][66] over dead qkv ----
    #pragma unroll
    for (int mt = 0; mt < 2; mt++) {
        int r0 = (half * 2 + mt) * 16 + grp;
        int r1 = r0 + 8;
        #pragma unroll
        for (int nt = 0; nt < 8; nt++) {
            int c0 = nt * 8 + 2 * tig;
            if (r0 < NTOK)
                *reinterpret_cast<float2*>(pool + r0 * OS_STRIDE + c0)
                    = make_float2(dv[mt][nt][0], dv[mt][nt][1]);
            if (r1 < NTOK)
                *reinterpret_cast<float2*>(pool + r1 * OS_STRIDE + c0)
                    = make_float2(dv[mt][nt][2], dv[mt][nt][3]);
        }
    }
    __syncthreads();   // B2: all os complete (residual reads all pools)

    // ---- residual + store: segment = (c, ph); warp handles 28 consecutive w ----
    // s in [0,512): c = s>>3 in 0..63, ph = s&7 (slot 7 skipped).
    {
        const float* xb = x   + (size_t)b * CH * HWPIX;
        float*       ob = out + (size_t)b * CH * HWPIX;
        for (int s = wid; s < 512; s += 8) {
            int c  = s >> 3;
            int ph = s & 7;
            if (ph < 7 && lane < 28) {
                int wn = lane / 7;
                int t  = ph * 7 + (lane - wn * 7);
                float ov = sp[wn * PW4 + t * OS_STRIDE + c];
                size_t gi = (size_t)c * HWPIX + (size_t)(h0 + ph) * HWDIM + w0 + lane;
                ob[gi] = ov + __ldg(&xb[gi]);
            }
        }
    }
}

extern "C" void kernel_launch(void* const* d_in, const int* in_sizes, int n_in,
                              void* d_out, int out_size)
{
    const float* x     = (const float*)d_in[0];
    const float* Wq    = (const float*)d_in[1];
    const float* bq    = (const float*)d_in[2];
    const float* Wk    = (const float*)d_in[3];
    const float* bk    = (const float*)d_in[4];
    const float* Wv    = (const float*)d_in[5];
    const float* bv    = (const float*)d_in[6];
    const float* gamma = (const float*)d_in[7];
    float* out = (float*)d_out;

    cudaFuncSetAttribute(proj_kernel, cudaFuncAttributeMaxDynamicSharedMemorySize, K1_SMEM_BYTES);
    cudaFuncSetAttribute(attn_kernel, cudaFuncAttributeMaxDynamicSharedMemorySize, K2_SMEM_BYTES);

    proj_kernel<<<NB * (HWPIX / 128), 128, K1_SMEM_BYTES>>>(x, Wq, bq, Wk, bk, Wv, bv);
    attn_kernel<<<NB * 32 * 8, 256, K2_SMEM_BYTES>>>(x, gamma, out);
}

// round 15
// speedup vs baseline: 1.1654x; 1.1654x over previous
#include <cuda_runtime.h>
#include <cstdint>

typedef unsigned long long u64;
typedef unsigned int u32;

#define HWDIM 224
#define HWPIX (HWDIM*HWDIM)   // 50176
#define NB    16
#define NTOK  49
#define CH    64
#define NOUT  80               // q(0..7) k(8..15) v(16..79)

// scratch: pixel-linear qkv [b][hw][80]
__device__ float g_qkv[(size_t)NB * HWPIX * NOUT];

__device__ __forceinline__ float tf32r(float f){
    u32 r;
    asm("cvt.rna.tf32.f32 %0, %1;" : "=r"(r) : "f"(f));
    return __uint_as_float(r);
}
__device__ __forceinline__ void mma_tf32(float* d, const u32* a, u32 b0, u32 b1){
    asm volatile(
        "mma.sync.aligned.m16n8k8.row.col.f32.tf32.tf32.f32 "
        "{%0,%1,%2,%3}, {%4,%5,%6,%7}, {%8,%9}, {%0,%1,%2,%3};"
        : "+f"(d[0]), "+f"(d[1]), "+f"(d[2]), "+f"(d[3])
        : "r"(a[0]), "r"(a[1]), "r"(a[2]), "r"(a[3]), "r"(b0), "r"(b1));
}

// ===================== K1: fused QKV projection (unchanged, tf32) =============
#define WCT_S 84
#define XT_S  67
#define OFF_XT   5376
#define OFF_BIAS 13952
#define OS1_S    84
#define K1_SMEM_FLOATS 14032
#define K1_SMEM_BYTES  (K1_SMEM_FLOATS*4)   // 56128

__global__ void __launch_bounds__(128, 4)
proj_kernel(const float* __restrict__ x,
            const float* __restrict__ Wq, const float* __restrict__ bq,
            const float* __restrict__ Wk, const float* __restrict__ bk,
            const float* __restrict__ Wv, const float* __restrict__ bv)
{
    extern __shared__ float s1[];
    const int tid = threadIdx.x;
    const int blk = blockIdx.x;               // 16 * 392
    const int b   = blk / 392;
    const int hw0 = (blk - b * 392) * 128;

    for (int idx = tid; idx < 512; idx += 128) {
        int o = idx >> 6, c = idx & 63;
        s1[c * WCT_S + o]     = tf32r(__ldg(&Wq[idx]));
        s1[c * WCT_S + 8 + o] = tf32r(__ldg(&Wk[idx]));
    }
    for (int idx = tid; idx < 4096; idx += 128) {
        int o = idx >> 6, c = idx & 63;
        s1[c * WCT_S + 16 + o] = tf32r(__ldg(&Wv[idx]));
    }
    if (tid < 80)
        s1[OFF_BIAS + tid] = (tid < 8)  ? __ldg(&bq[tid])
                           : (tid < 16) ? __ldg(&bk[tid - 8])
                                        : __ldg(&bv[tid - 16]);
    {
        const float* xb = x + (size_t)b * CH * HWPIX + hw0 + tid;
        float* xr = s1 + OFF_XT + tid * XT_S;
        #pragma unroll 8
        for (int c = 0; c < CH; c++)
            xr[c] = tf32r(__ldg(xb + (size_t)c * HWPIX));
    }
    __syncthreads();

    const int wid  = tid >> 5, lane = tid & 31;
    const int grp  = lane >> 2;
    const int tig  = lane & 3;
    const int pb   = wid * 32;

    float d[2][10][4];
    #pragma unroll
    for (int mt = 0; mt < 2; mt++)
        #pragma unroll
        for (int nt = 0; nt < 10; nt++)
            #pragma unroll
            for (int e = 0; e < 4; e++) d[mt][nt][e] = 0.0f;

    const u32* xtu = reinterpret_cast<const u32*>(s1 + OFF_XT);
    const u32* wcu = reinterpret_cast<const u32*>(s1);

    #pragma unroll
    for (int k0 = 0; k0 < 64; k0 += 8) {
        u32 a[2][4];
        #pragma unroll
        for (int mt = 0; mt < 2; mt++) {
            int base = pb + mt * 16;
            a[mt][0] = xtu[(base + grp)     * XT_S + k0 + tig];
            a[mt][1] = xtu[(base + grp + 8) * XT_S + k0 + tig];
            a[mt][2] = xtu[(base + grp)     * XT_S + k0 + tig + 4];
            a[mt][3] = xtu[(base + grp + 8) * XT_S + k0 + tig + 4];
        }
        #pragma unroll
        for (int nt = 0; nt < 10; nt++) {
            u32 b0 = wcu[(k0 + tig)     * WCT_S + nt * 8 + grp];
            u32 b1 = wcu[(k0 + tig + 4) * WCT_S + nt * 8 + grp];
            mma_tf32(d[0][nt], a[0], b0, b1);
            mma_tf32(d[1][nt], a[1], b0, b1);
        }
    }
    __syncthreads();

    const float* sb = s1 + OFF_BIAS;
    #pragma unroll
    for (int mt = 0; mt < 2; mt++) {
        int p0 = pb + mt * 16 + grp;
        #pragma unroll
        for (int nt = 0; nt < 10; nt++) {
            int n0 = nt * 8 + 2 * tig;
            float b0v = sb[n0], b1v = sb[n0 + 1];
            *reinterpret_cast<float2*>(s1 + p0 * OS1_S + n0)
                = make_float2(d[mt][nt][0] + b0v, d[mt][nt][1] + b1v);
            *reinterpret_cast<float2*>(s1 + (p0 + 8) * OS1_S + n0)
                = make_float2(d[mt][nt][2] + b0v, d[mt][nt][3] + b1v);
        }
    }
    __syncthreads();

    float4* dst = reinterpret_cast<float4*>(g_qkv + ((size_t)b * HWPIX + hw0) * NOUT);
    for (int i = tid; i < 2560; i += 128) {
        int p  = i / 20;
        int c4 = i - p * 20;
        dst[i] = *reinterpret_cast<const float4*>(s1 + p * OS1_S + c4 * 4);
    }
}

// ===================== K2: attention — 2 windows per WARP-interleaved block ===
// 128 threads = 4 warps; warp w owns m-tile rows [w*16, w*16+16) for BOTH windows.
// Per-window pool (6768 floats): qkv[49][80]@0 (3920) | att[49][58]@3920 (2848)
// os[49][66] overlays qkv after AV.
#define QKV_S 80
#define AT_S  58
#define ATT_OFF 3920
#define OS_S  66
#define PW 6768
#define K2_SMEM_FLOATS (2*PW)               // 13536
#define K2_SMEM_BYTES  (K2_SMEM_FLOATS*4)   // 54144

__global__ void __launch_bounds__(128, 4)
attn_kernel(const float* __restrict__ x,
            const float* __restrict__ gamma,
            float* __restrict__ out)
{
    extern __shared__ float sp[];
    const int tid = threadIdx.x;
    const int blk = blockIdx.x;        // 16 b * 32 wh * 16 wpair
    const int b   = blk >> 9;
    const int rem = blk & 511;
    const int wh  = rem >> 4;
    const int wp  = rem & 15;
    const int h0  = wh * 7;
    const int w0  = wp * 14;

    const float g = __ldg(gamma);

    const int wid  = tid >> 5, lane = tid & 31;
    const int grp  = lane >> 2, tig = lane & 3;
    const int w16  = wid * 16;         // this warp's m-tile base row

    float* att0 = sp + ATT_OFF;
    float* att1 = sp + PW + ATT_OFF;
    const u32* pu0 = reinterpret_cast<const u32*>(sp);
    const u32* pu1 = reinterpret_cast<const u32*>(sp + PW);

    // ---- stage qkv: 7 rows x 14 px x 80 floats contiguous ----
    const float* gq = g_qkv + ((size_t)b * HWPIX + (size_t)h0 * HWDIM + w0) * NOUT;
    for (int i = tid; i < 1960; i += 128) {
        int ph = i / 280;
        int rr = i - ph * 280;
        int pw = rr / 20;
        int c4 = rr - pw * 20;
        int wn = (pw >= 7);
        int t  = ph * 7 + pw - 7 * wn;
        float4 v = __ldg(reinterpret_cast<const float4*>(gq + ((size_t)ph * HWDIM + pw) * NOUT) + c4);
        *reinterpret_cast<float4*>(sp + wn * PW + t * QKV_S + c4 * 4) = v;
    }
    __syncthreads();   // B1: staging visible

    // ---- QK^T: both windows interleaved; rows [w16, w16+16) ----
    {
        const int r0 = w16 + grp, r1 = r0 + 8;
        const int r0c = min(r0, 48), r1c = min(r1, 48);
        u32 aq0[4], aq1[4];
        aq0[0] = pu0[r0c * QKV_S + tig];
        aq0[1] = pu0[r1c * QKV_S + tig];
        aq0[2] = pu0[r0c * QKV_S + tig + 4];
        aq0[3] = pu0[r1c * QKV_S + tig + 4];
        aq1[0] = pu1[r0c * QKV_S + tig];
        aq1[1] = pu1[r1c * QKV_S + tig];
        aq1[2] = pu1[r0c * QKV_S + tig + 4];
        aq1[3] = pu1[r1c * QKV_S + tig + 4];

        float dq[2][7][4];
        #pragma unroll
        for (int wn = 0; wn < 2; wn++)
            #pragma unroll
            for (int nt = 0; nt < 7; nt++)
                #pragma unroll
                for (int e = 0; e < 4; e++) dq[wn][nt][e] = 0.0f;

        #pragma unroll
        for (int nt = 0; nt < 7; nt++) {
            int m = nt * 8 + grp;
            bool mv = (m < NTOK);
            u32 b00 = mv ? pu0[m * QKV_S + 8 + tig]     : 0;
            u32 b01 = mv ? pu0[m * QKV_S + 8 + tig + 4] : 0;
            u32 b10 = mv ? pu1[m * QKV_S + 8 + tig]     : 0;
            u32 b11 = mv ? pu1[m * QKV_S + 8 + tig + 4] : 0;
            mma_tf32(dq[0][nt], aq0, b00, b01);
            mma_tf32(dq[1][nt], aq1, b10, b11);
        }
        // store (cols unpredicated: pad cols get exact zeros)
        #pragma unroll
        for (int nt = 0; nt < 7; nt++) {
            int c0 = nt * 8 + 2 * tig;
            if (r0 < NTOK) {
                *reinterpret_cast<float2*>(att0 + r0 * AT_S + c0) = make_float2(dq[0][nt][0], dq[0][nt][1]);
                *reinterpret_cast<float2*>(att1 + r0 * AT_S + c0) = make_float2(dq[1][nt][0], dq[1][nt][1]);
            }
            if (r1 < NTOK) {
                *reinterpret_cast<float2*>(att0 + r1 * AT_S + c0) = make_float2(dq[0][nt][2], dq[0][nt][3]);
                *reinterpret_cast<float2*>(att1 + r1 * AT_S + c0) = make_float2(dq[1][nt][2], dq[1][nt][3]);
            }
        }
    }
    __syncwarp();      // rows warp-local

    // ---- softmax: lane<16 -> window0 row w16+lane; lane>=16 -> window1 ----
    {
        int row = w16 + (lane & 15);
        float* ar = ((lane >> 4) ? att1 : att0) + row * AT_S;
        if (row < NTOK) {
            float mx = ar[0];
            #pragma unroll 7
            for (int m = 1; m < NTOK; m++) mx = fmaxf(mx, ar[m]);
            float s = 0.0f;
            #pragma unroll 7
            for (int m = 0; m < NTOK; m++) {
                float e = __expf(ar[m] - mx);
                ar[m] = e;
                s += e;
            }
            float rs = g / s;
            #pragma unroll 7
            for (int m = 0; m < NTOK; m++) ar[m] = tf32r(ar[m] * rs);
        }
    }
    __syncwarp();

    // ---- AV: both windows interleaved ----
    float dv[2][8][4];
    #pragma unroll
    for (int wn = 0; wn < 2; wn++)
        #pragma unroll
        for (int nt = 0; nt < 8; nt++)
            #pragma unroll
            for (int e = 0; e < 4; e++) dv[wn][nt][e] = 0.0f;
    {
        const u32* au0 = reinterpret_cast<const u32*>(att0);
        const u32* au1 = reinterpret_cast<const u32*>(att1);
        const int r0 = w16 + grp;
        const int r0c = min(r0, 48), r1c = min(r0 + 8, 48);
        #pragma unroll
        for (int ks = 0; ks < 7; ks++) {
            int k0 = ks * 8;
            u32 a0[4], a1[4];
            a0[0] = au0[r0c * AT_S + k0 + tig];
            a0[1] = au0[r1c * AT_S + k0 + tig];
            a0[2] = au0[r0c * AT_S + k0 + tig + 4];
            a0[3] = au0[r1c * AT_S + k0 + tig + 4];
            a1[0] = au1[r0c * AT_S + k0 + tig];
            a1[1] = au1[r1c * AT_S + k0 + tig];
            a1[2] = au1[r0c * AT_S + k0 + tig + 4];
            a1[3] = au1[r1c * AT_S + k0 + tig + 4];
            #pragma unroll
            for (int nt = 0; nt < 8; nt++) {
                int c = nt * 8 + grp;
                int m0 = k0 + tig;
                u32 b00, b01, b10, b11;
                if (ks < 6) {
                    b00 = pu0[m0 * QKV_S + 16 + c];
                    b01 = pu0[(m0 + 4) * QKV_S + 16 + c];
                    b10 = pu1[m0 * QKV_S + 16 + c];
                    b11 = pu1[(m0 + 4) * QKV_S + 16 + c];
                } else {
                    bool mv = (m0 < NTOK);   // only m=48 real
                    b00 = mv ? pu0[m0 * QKV_S + 16 + c] : 0;
                    b10 = mv ? pu1[m0 * QKV_S + 16 + c] : 0;
                    b01 = 0; b11 = 0;
                }
                mma_tf32(dv[0][nt], a0, b00, b01);
                mma_tf32(dv[1][nt], a1, b10, b11);
            }
        }
    }
    __syncthreads();   // B2: all v reads done -> os overlays qkv

    // ---- epilogue: os[t][66] over dead qkv ----
    {
        const int r0 = w16 + grp, r1 = r0 + 8;
        #pragma unroll
        for (int nt = 0; nt < 8; nt++) {
            int c0 = nt * 8 + 2 * tig;
            if (r0 < NTOK) {
                *reinterpret_cast<float2*>(sp + r0 * OS_S + c0)      = make_float2(dv[0][nt][0], dv[0][nt][1]);
                *reinterpret_cast<float2*>(sp + PW + r0 * OS_S + c0) = make_float2(dv[1][nt][0], dv[1][nt][1]);
            }
            if (r1 < NTOK) {
                *reinterpret_cast<float2*>(sp + r1 * OS_S + c0)      = make_float2(dv[0][nt][2], dv[0][nt][3]);
                *reinterpret_cast<float2*>(sp + PW + r1 * OS_S + c0) = make_float2(dv[1][nt][2], dv[1][nt][3]);
            }
        }
    }
    __syncthreads();   // B3: os complete

    // ---- residual + store: u = cr*98 + (ph*14 + pwx); 14-px contiguous lanes ----
    {
        const float* xb = x   + (size_t)b * CH * HWPIX;
        float*       ob = out + (size_t)b * CH * HWPIX;
        for (int u = tid; u < 392; u += 128) {
            int cr  = u / 98;             // 16-channel run index
            int p14 = u - cr * 98;        // 0..97
            int ph  = p14 / 14;
            int pwx = p14 - ph * 14;
            int wn  = (pwx >= 7);
            int t   = ph * 7 + pwx - 7 * wn;
            const float* osr = sp + wn * PW + t * OS_S + cr * 16;
            size_t gi = (size_t)(cr * 16) * HWPIX + (size_t)(h0 + ph) * HWDIM + w0 + pwx;
            #pragma unroll
            for (int c = 0; c < 16; c++) {
                ob[gi] = osr[c] + __ldg(&xb[gi]);
                gi += HWPIX;
            }
        }
    }
}

extern "C" void kernel_launch(void* const* d_in, const int* in_sizes, int n_in,
                              void* d_out, int out_size)
{
    const float* x     = (const float*)d_in[0];
    const float* Wq    = (const float*)d_in[1];
    const float* bq    = (const float*)d_in[2];
    const float* Wk    = (const float*)d_in[3];
    const float* bk    = (const float*)d_in[4];
    const float* Wv    = (const float*)d_in[5];
    const float* bv    = (const float*)d_in[6];
    const float* gamma = (const float*)d_in[7];
    float* out = (float*)d_out;

    cudaFuncSetAttribute(proj_kernel, cudaFuncAttributeMaxDynamicSharedMemorySize, K1_SMEM_BYTES);
    cudaFuncSetAttribute(attn_kernel, cudaFuncAttributeMaxDynamicSharedMemorySize, K2_SMEM_BYTES);

    proj_kernel<<<NB * (HWPIX / 128), 128, K1_SMEM_BYTES>>>(x, Wq, bq, Wk, bk, Wv, bv);
    attn_kernel<<<NB * 32 * 16, 128, K2_SMEM_BYTES>>>(x, gamma, out);
}

// round 16
// speedup vs baseline: 1.2732x; 1.0925x over previous
#include <cuda_runtime.h>
#include <cstdint>

typedef unsigned long long u64;
typedef unsigned int u32;

#define HWDIM 224
#define HWPIX (HWDIM*HWDIM)   // 50176
#define NB    16
#define NTOK  49
#define CH    64
#define NOUT  80               // q(0..7) k(8..15) v(16..79)

// scratch: pixel-linear qkv, 48 u32/px: [q0..q7,k0..k7 fp32][v as 32 bf16x2]
#define QKV_W 48
__device__ u32 g_qkv[(size_t)NB * HWPIX * QKV_W];

__device__ __forceinline__ float tf32r(float f){
    u32 r;
    asm("cvt.rna.tf32.f32 %0, %1;" : "=r"(r) : "f"(f));
    return __uint_as_float(r);
}
__device__ __forceinline__ u32 bf16x2_rn(float lo, float hi){
    u32 r;
    asm("cvt.rn.bf16x2.f32 %0, %1, %2;" : "=r"(r) : "f"(hi), "f"(lo));
    return r;
}
__device__ __forceinline__ void mma_tf32(float* d, const u32* a, u32 b0, u32 b1){
    asm volatile(
        "mma.sync.aligned.m16n8k8.row.col.f32.tf32.tf32.f32 "
        "{%0,%1,%2,%3}, {%4,%5,%6,%7}, {%8,%9}, {%0,%1,%2,%3};"
        : "+f"(d[0]), "+f"(d[1]), "+f"(d[2]), "+f"(d[3])
        : "r"(a[0]), "r"(a[1]), "r"(a[2]), "r"(a[3]), "r"(b0), "r"(b1));
}

// ===================== K1: fused QKV projection (tf32, bf16-V output) =========
#define WCT_S 84
#define XT_S  67
#define OFF_XT   5376
#define OFF_BIAS 13952
#define OSW_S    52            // u32 stride of packed output row
#define K1_SMEM_FLOATS 14032
#define K1_SMEM_BYTES  (K1_SMEM_FLOATS*4)   // 56128

__global__ void __launch_bounds__(128, 4)
proj_kernel(const float* __restrict__ x,
            const float* __restrict__ Wq, const float* __restrict__ bq,
            const float* __restrict__ Wk, const float* __restrict__ bk,
            const float* __restrict__ Wv, const float* __restrict__ bv)
{
    extern __shared__ float s1[];
    u32* s1u = reinterpret_cast<u32*>(s1);
    const int tid = threadIdx.x;
    const int blk = blockIdx.x;               // 16 * 392
    const int b   = blk / 392;
    const int hw0 = (blk - b * 392) * 128;

    for (int idx = tid; idx < 512; idx += 128) {
        int o = idx >> 6, c = idx & 63;
        s1[c * WCT_S + o]     = tf32r(__ldg(&Wq[idx]));
        s1[c * WCT_S + 8 + o] = tf32r(__ldg(&Wk[idx]));
    }
    for (int idx = tid; idx < 4096; idx += 128) {
        int o = idx >> 6, c = idx & 63;
        s1[c * WCT_S + 16 + o] = tf32r(__ldg(&Wv[idx]));
    }
    if (tid < 80)
        s1[OFF_BIAS + tid] = (tid < 8)  ? __ldg(&bq[tid])
                           : (tid < 16) ? __ldg(&bk[tid - 8])
                                        : __ldg(&bv[tid - 16]);
    {
        const float* xb = x + (size_t)b * CH * HWPIX + hw0 + tid;
        float* xr = s1 + OFF_XT + tid * XT_S;
        #pragma unroll 8
        for (int c = 0; c < CH; c++)
            xr[c] = tf32r(__ldg(xb + (size_t)c * HWPIX));
    }
    __syncthreads();

    const int wid  = tid >> 5, lane = tid & 31;
    const int grp  = lane >> 2;
    const int tig  = lane & 3;
    const int pb   = wid * 32;

    float d[2][10][4];
    #pragma unroll
    for (int mt = 0; mt < 2; mt++)
        #pragma unroll
        for (int nt = 0; nt < 10; nt++)
            #pragma unroll
            for (int e = 0; e < 4; e++) d[mt][nt][e] = 0.0f;

    const u32* xtu = reinterpret_cast<const u32*>(s1 + OFF_XT);
    const u32* wcu = reinterpret_cast<const u32*>(s1);

    #pragma unroll
    for (int k0 = 0; k0 < 64; k0 += 8) {
        u32 a[2][4];
        #pragma unroll
        for (int mt = 0; mt < 2; mt++) {
            int base = pb + mt * 16;
            a[mt][0] = xtu[(base + grp)     * XT_S + k0 + tig];
            a[mt][1] = xtu[(base + grp + 8) * XT_S + k0 + tig];
            a[mt][2] = xtu[(base + grp)     * XT_S + k0 + tig + 4];
            a[mt][3] = xtu[(base + grp + 8) * XT_S + k0 + tig + 4];
        }
        #pragma unroll
        for (int nt = 0; nt < 10; nt++) {
            u32 b0 = wcu[(k0 + tig)     * WCT_S + nt * 8 + grp];
            u32 b1 = wcu[(k0 + tig + 4) * WCT_S + nt * 8 + grp];
            mma_tf32(d[0][nt], a[0], b0, b1);
            mma_tf32(d[1][nt], a[1], b0, b1);
        }
    }
    __syncthreads();   // xt/wct reads done; packed-out overlays them

    // epilogue: packed row per px: u32[0..15] qk fp32, u32[16..47] v bf16x2
    const float* sb = s1 + OFF_BIAS;
    #pragma unroll
    for (int mt = 0; mt < 2; mt++) {
        int p0 = pb + mt * 16 + grp;
        int p1 = p0 + 8;
        #pragma unroll
        for (int nt = 0; nt < 10; nt++) {
            int n0 = nt * 8 + 2 * tig;
            float b0v = sb[n0], b1v = sb[n0 + 1];
            float v00 = d[mt][nt][0] + b0v, v01 = d[mt][nt][1] + b1v;
            float v10 = d[mt][nt][2] + b0v, v11 = d[mt][nt][3] + b1v;
            if (nt < 2) {
                int wi = nt * 8 + 2 * tig;   // q: 0..7, k: 8..15
                *reinterpret_cast<float2*>(s1u + p0 * OSW_S + wi) = make_float2(v00, v01);
                *reinterpret_cast<float2*>(s1u + p1 * OSW_S + wi) = make_float2(v10, v11);
            } else {
                int wi = 16 + (nt - 2) * 4 + tig;
                s1u[p0 * OSW_S + wi] = bf16x2_rn(v00, v01);
                s1u[p1 * OSW_S + wi] = bf16x2_rn(v10, v11);
            }
        }
    }
    __syncthreads();

    // coalesced stream: 128 px * 12 uint4 (48 u32) contiguous
    uint4* dst = reinterpret_cast<uint4*>(g_qkv + ((size_t)b * HWPIX + hw0) * QKV_W);
    for (int i = tid; i < 1536; i += 128) {
        int p  = i / 12;
        int w4 = i - p * 12;
        dst[i] = *reinterpret_cast<const uint4*>(s1u + p * OSW_S + w4 * 4);
    }
}

// ===================== K2: attention — 2 windows / warp-interleaved ===========
#define QKV_S 80
#define AT_S  58
#define ATT_OFF 3920
#define OS_S  66
#define PW 6768
#define K2_SMEM_FLOATS (2*PW)               // 13536
#define K2_SMEM_BYTES  (K2_SMEM_FLOATS*4)   // 54144

__global__ void __launch_bounds__(128, 4)
attn_kernel(const float* __restrict__ x,
            const float* __restrict__ gamma,
            float* __restrict__ out)
{
    extern __shared__ float sp[];
    const int tid = threadIdx.x;
    const int blk = blockIdx.x;        // 16 b * 32 wh * 16 wpair
    const int b   = blk >> 9;
    const int rem = blk & 511;
    const int wh  = rem >> 4;
    const int wp  = rem & 15;
    const int h0  = wh * 7;
    const int w0  = wp * 14;

    const float g = __ldg(gamma);

    const int wid  = tid >> 5, lane = tid & 31;
    const int grp  = lane >> 2, tig = lane & 3;
    const int w16  = wid * 16;

    float* att0 = sp + ATT_OFF;
    float* att1 = sp + PW + ATT_OFF;
    const u32* pu0 = reinterpret_cast<const u32*>(sp);
    const u32* pu1 = reinterpret_cast<const u32*>(sp + PW);

    // ---- stage packed qkv: 98 px * 12 uint4; up-convert v bf16->fp32 ----
    const u32* gq = g_qkv + ((size_t)b * HWPIX + (size_t)h0 * HWDIM + w0) * QKV_W;
    for (int i = tid; i < 1176; i += 128) {
        int ph = i / 168;
        int rr = i - ph * 168;
        int pw = rr / 12;
        int w4 = rr - pw * 12;
        int wn = (pw >= 7);
        int t  = ph * 7 + pw - 7 * wn;
        uint4 v = __ldg(reinterpret_cast<const uint4*>(gq + ((size_t)ph * HWDIM + pw) * QKV_W) + w4);
        float* dstp = sp + wn * PW + t * QKV_S;
        if (w4 < 4) {
            *reinterpret_cast<uint4*>(dstp + w4 * 4) = v;   // qk fp32 passthrough
        } else {
            int c0 = 16 + (w4 - 4) * 8;
            float4 lo, hi;
            lo.x = __uint_as_float(v.x << 16); lo.y = __uint_as_float(v.x & 0xffff0000u);
            lo.z = __uint_as_float(v.y << 16); lo.w = __uint_as_float(v.y & 0xffff0000u);
            hi.x = __uint_as_float(v.z << 16); hi.y = __uint_as_float(v.z & 0xffff0000u);
            hi.z = __uint_as_float(v.w << 16); hi.w = __uint_as_float(v.w & 0xffff0000u);
            *reinterpret_cast<float4*>(dstp + c0)     = lo;
            *reinterpret_cast<float4*>(dstp + c0 + 4) = hi;
        }
    }
    __syncthreads();   // B1: staging visible

    // ---- QK^T: both windows interleaved; rows [w16, w16+16) ----
    {
        const int r0 = w16 + grp, r1 = r0 + 8;
        const int r0c = min(r0, 48), r1c = min(r1, 48);
        u32 aq0[4], aq1[4];
        aq0[0] = pu0[r0c * QKV_S + tig];
        aq0[1] = pu0[r1c * QKV_S + tig];
        aq0[2] = pu0[r0c * QKV_S + tig + 4];
        aq0[3] = pu0[r1c * QKV_S + tig + 4];
        aq1[0] = pu1[r0c * QKV_S + tig];
        aq1[1] = pu1[r1c * QKV_S + tig];
        aq1[2] = pu1[r0c * QKV_S + tig + 4];
        aq1[3] = pu1[r1c * QKV_S + tig + 4];

        float dq[2][7][4];
        #pragma unroll
        for (int wn = 0; wn < 2; wn++)
            #pragma unroll
            for (int nt = 0; nt < 7; nt++)
                #pragma unroll
                for (int e = 0; e < 4; e++) dq[wn][nt][e] = 0.0f;

        #pragma unroll
        for (int nt = 0; nt < 7; nt++) {
            int m = nt * 8 + grp;
            bool mv = (m < NTOK);
            u32 b00 = mv ? pu0[m * QKV_S + 8 + tig]     : 0;
            u32 b01 = mv ? pu0[m * QKV_S + 8 + tig + 4] : 0;
            u32 b10 = mv ? pu1[m * QKV_S + 8 + tig]     : 0;
            u32 b11 = mv ? pu1[m * QKV_S + 8 + tig + 4] : 0;
            mma_tf32(dq[0][nt], aq0, b00, b01);
            mma_tf32(dq[1][nt], aq1, b10, b11);
        }
        #pragma unroll
        for (int nt = 0; nt < 7; nt++) {
            int c0 = nt * 8 + 2 * tig;
            if (r0 < NTOK) {
                *reinterpret_cast<float2*>(att0 + r0 * AT_S + c0) = make_float2(dq[0][nt][0], dq[0][nt][1]);
                *reinterpret_cast<float2*>(att1 + r0 * AT_S + c0) = make_float2(dq[1][nt][0], dq[1][nt][1]);
            }
            if (r1 < NTOK) {
                *reinterpret_cast<float2*>(att0 + r1 * AT_S + c0) = make_float2(dq[0][nt][2], dq[0][nt][3]);
                *reinterpret_cast<float2*>(att1 + r1 * AT_S + c0) = make_float2(dq[1][nt][2], dq[1][nt][3]);
            }
        }
    }
    __syncwarp();

    // ---- softmax: lane<16 -> window0 row w16+lane&15; else window1 ----
    {
        int row = w16 + (lane & 15);
        float* ar = ((lane >> 4) ? att1 : att0) + row * AT_S;
        if (row < NTOK) {
            float mx = ar[0];
            #pragma unroll 7
            for (int m = 1; m < NTOK; m++) mx = fmaxf(mx, ar[m]);
            float s = 0.0f;
            #pragma unroll 7
            for (int m = 0; m < NTOK; m++) {
                float e = __expf(ar[m] - mx);
                ar[m] = e;
                s += e;
            }
            float rs = g / s;
            #pragma unroll 7
            for (int m = 0; m < NTOK; m++) ar[m] = tf32r(ar[m] * rs);
        }
    }
    __syncwarp();

    // ---- AV: both windows interleaved ----
    float dv[2][8][4];
    #pragma unroll
    for (int wn = 0; wn < 2; wn++)
        #pragma unroll
        for (int nt = 0; nt < 8; nt++)
            #pragma unroll
            for (int e = 0; e < 4; e++) dv[wn][nt][e] = 0.0f;
    {
        const u32* au0 = reinterpret_cast<const u32*>(att0);
        const u32* au1 = reinterpret_cast<const u32*>(att1);
        const int r0 = w16 + grp;
        const int r0c = min(r0, 48), r1c = min(r0 + 8, 48);
        #pragma unroll
        for (int ks = 0; ks < 7; ks++) {
            int k0 = ks * 8;
            u32 a0[4], a1[4];
            a0[0] = au0[r0c * AT_S + k0 + tig];
            a0[1] = au0[r1c * AT_S + k0 + tig];
            a0[2] = au0[r0c * AT_S + k0 + tig + 4];
            a0[3] = au0[r1c * AT_S + k0 + tig + 4];
            a1[0] = au1[r0c * AT_S + k0 + tig];
            a1[1] = au1[r1c * AT_S + k0 + tig];
            a1[2] = au1[r0c * AT_S + k0 + tig + 4];
            a1[3] = au1[r1c * AT_S + k0 + tig + 4];
            #pragma unroll
            for (int nt = 0; nt < 8; nt++) {
                int c = nt * 8 + grp;
                int m0 = k0 + tig;
                u32 b00, b01, b10, b11;
                if (ks < 6) {
                    b00 = pu0[m0 * QKV_S + 16 + c];
                    b01 = pu0[(m0 + 4) * QKV_S + 16 + c];
                    b10 = pu1[m0 * QKV_S + 16 + c];
                    b11 = pu1[(m0 + 4) * QKV_S + 16 + c];
                } else {
                    bool mv = (m0 < NTOK);   // only m=48 real
                    b00 = mv ? pu0[m0 * QKV_S + 16 + c] : 0;
                    b10 = mv ? pu1[m0 * QKV_S + 16 + c] : 0;
                    b01 = 0; b11 = 0;
                }
                mma_tf32(dv[0][nt], a0, b00, b01);
                mma_tf32(dv[1][nt], a1, b10, b11);
            }
        }
    }
    __syncthreads();   // B2: v reads done -> os overlays qkv

    // ---- epilogue: os[t][66] over dead qkv ----
    {
        const int r0 = w16 + grp, r1 = r0 + 8;
        #pragma unroll
        for (int nt = 0; nt < 8; nt++) {
            int c0 = nt * 8 + 2 * tig;
            if (r0 < NTOK) {
                *reinterpret_cast<float2*>(sp + r0 * OS_S + c0)      = make_float2(dv[0][nt][0], dv[0][nt][1]);
                *reinterpret_cast<float2*>(sp + PW + r0 * OS_S + c0) = make_float2(dv[1][nt][0], dv[1][nt][1]);
            }
            if (r1 < NTOK) {
                *reinterpret_cast<float2*>(sp + r1 * OS_S + c0)      = make_float2(dv[0][nt][2], dv[0][nt][3]);
                *reinterpret_cast<float2*>(sp + PW + r1 * OS_S + c0) = make_float2(dv[1][nt][2], dv[1][nt][3]);
            }
        }
    }
    __syncthreads();   // B3: os complete

    // ---- residual + store: 14-px contiguous lanes, 16-channel runs ----
    {
        const float* xb = x   + (size_t)b * CH * HWPIX;
        float*       ob = out + (size_t)b * CH * HWPIX;
        for (int u = tid; u < 392; u += 128) {
            int cr  = u / 98;
            int p14 = u - cr * 98;
            int ph  = p14 / 14;
            int pwx = p14 - ph * 14;
            int wn  = (pwx >= 7);
            int t   = ph * 7 + pwx - 7 * wn;
            const float* osr = sp + wn * PW + t * OS_S + cr * 16;
            size_t gi = (size_t)(cr * 16) * HWPIX + (size_t)(h0 + ph) * HWDIM + w0 + pwx;
            #pragma unroll
            for (int c = 0; c < 16; c++) {
                ob[gi] = osr[c] + __ldg(&xb[gi]);
                gi += HWPIX;
            }
        }
    }
}

extern "C" void kernel_launch(void* const* d_in, const int* in_sizes, int n_in,
                              void* d_out, int out_size)
{
    const float* x     = (const float*)d_in[0];
    const float* Wq    = (const float*)d_in[1];
    const float* bq    = (const float*)d_in[2];
    const float* Wk    = (const float*)d_in[3];
    const float* bk    = (const float*)d_in[4];
    const float* Wv    = (const float*)d_in[5];
    const float* bv    = (const float*)d_in[6];
    const float* gamma = (const float*)d_in[7];
    float* out = (float*)d_out;

    cudaFuncSetAttribute(proj_kernel, cudaFuncAttributeMaxDynamicSharedMemorySize, K1_SMEM_BYTES);
    cudaFuncSetAttribute(attn_kernel, cudaFuncAttributeMaxDynamicSharedMemorySize, K2_SMEM_BYTES);

    proj_kernel<<<NB * (HWPIX / 128), 128, K1_SMEM_BYTES>>>(x, Wq, bq, Wk, bk, Wv, bv);
    attn_kernel<<<NB * 32 * 16, 128, K2_SMEM_BYTES>>>(x, gamma, out);
}

// round 17
// speedup vs baseline: 1.3723x; 1.0778x over previous
#include <cuda_runtime.h>
#include <cstdint>

typedef unsigned long long u64;
typedef unsigned int u32;

#define HWDIM 224
#define HWPIX (HWDIM*HWDIM)   // 50176
#define NB    16
#define NTOK  49
#define CH    64
#define NOUT  80               // q(0..7) k(8..15) v(16..79)

// scratch: pixel-linear qkv, 48 u32/px: [q0..q7,k0..k7 fp32][v as 32 bf16x2]
#define QKV_W 48
__device__ u32 g_qkv[(size_t)NB * HWPIX * QKV_W];

__device__ __forceinline__ float tf32r(float f){
    u32 r;
    asm("cvt.rna.tf32.f32 %0, %1;" : "=r"(r) : "f"(f));
    return __uint_as_float(r);
}
__device__ __forceinline__ u32 bf16x2_rn(float lo, float hi){
    u32 r;
    asm("cvt.rn.bf16x2.f32 %0, %1, %2;" : "=r"(r) : "f"(hi), "f"(lo));
    return r;
}
__device__ __forceinline__ void mma_tf32(float* d, const u32* a, u32 b0, u32 b1){
    asm volatile(
        "mma.sync.aligned.m16n8k8.row.col.f32.tf32.tf32.f32 "
        "{%0,%1,%2,%3}, {%4,%5,%6,%7}, {%8,%9}, {%0,%1,%2,%3};"
        : "+f"(d[0]), "+f"(d[1]), "+f"(d[2]), "+f"(d[3])
        : "r"(a[0]), "r"(a[1]), "r"(a[2]), "r"(a[3]), "r"(b0), "r"(b1));
}

// ===================== K1: fused QKV projection (tf32, bf16-V output) =========
// (unchanged from round 16)
#define WCT_S 84
#define XT_S  67
#define OFF_XT   5376
#define OFF_BIAS 13952
#define OSW_S    52            // u32 stride of packed output row
#define K1_SMEM_FLOATS 14032
#define K1_SMEM_BYTES  (K1_SMEM_FLOATS*4)   // 56128

__global__ void __launch_bounds__(128, 4)
proj_kernel(const float* __restrict__ x,
            const float* __restrict__ Wq, const float* __restrict__ bq,
            const float* __restrict__ Wk, const float* __restrict__ bk,
            const float* __restrict__ Wv, const float* __restrict__ bv)
{
    extern __shared__ float s1[];
    u32* s1u = reinterpret_cast<u32*>(s1);
    const int tid = threadIdx.x;
    const int blk = blockIdx.x;               // 16 * 392
    const int b   = blk / 392;
    const int hw0 = (blk - b * 392) * 128;

    for (int idx = tid; idx < 512; idx += 128) {
        int o = idx >> 6, c = idx & 63;
        s1[c * WCT_S + o]     = tf32r(__ldg(&Wq[idx]));
        s1[c * WCT_S + 8 + o] = tf32r(__ldg(&Wk[idx]));
    }
    for (int idx = tid; idx < 4096; idx += 128) {
        int o = idx >> 6, c = idx & 63;
        s1[c * WCT_S + 16 + o] = tf32r(__ldg(&Wv[idx]));
    }
    if (tid < 80)
        s1[OFF_BIAS + tid] = (tid < 8)  ? __ldg(&bq[tid])
                           : (tid < 16) ? __ldg(&bk[tid - 8])
                                        : __ldg(&bv[tid - 16]);
    {
        const float* xb = x + (size_t)b * CH * HWPIX + hw0 + tid;
        float* xr = s1 + OFF_XT + tid * XT_S;
        #pragma unroll 8
        for (int c = 0; c < CH; c++)
            xr[c] = tf32r(__ldg(xb + (size_t)c * HWPIX));
    }
    __syncthreads();

    const int wid  = tid >> 5, lane = tid & 31;
    const int grp  = lane >> 2;
    const int tig  = lane & 3;
    const int pb   = wid * 32;

    float d[2][10][4];
    #pragma unroll
    for (int mt = 0; mt < 2; mt++)
        #pragma unroll
        for (int nt = 0; nt < 10; nt++)
            #pragma unroll
            for (int e = 0; e < 4; e++) d[mt][nt][e] = 0.0f;

    const u32* xtu = reinterpret_cast<const u32*>(s1 + OFF_XT);
    const u32* wcu = reinterpret_cast<const u32*>(s1);

    #pragma unroll
    for (int k0 = 0; k0 < 64; k0 += 8) {
        u32 a[2][4];
        #pragma unroll
        for (int mt = 0; mt < 2; mt++) {
            int base = pb + mt * 16;
            a[mt][0] = xtu[(base + grp)     * XT_S + k0 + tig];
            a[mt][1] = xtu[(base + grp + 8) * XT_S + k0 + tig];
            a[mt][2] = xtu[(base + grp)     * XT_S + k0 + tig + 4];
            a[mt][3] = xtu[(base + grp + 8) * XT_S + k0 + tig + 4];
        }
        #pragma unroll
        for (int nt = 0; nt < 10; nt++) {
            u32 b0 = wcu[(k0 + tig)     * WCT_S + nt * 8 + grp];
            u32 b1 = wcu[(k0 + tig + 4) * WCT_S + nt * 8 + grp];
            mma_tf32(d[0][nt], a[0], b0, b1);
            mma_tf32(d[1][nt], a[1], b0, b1);
        }
    }
    __syncthreads();   // xt/wct reads done; packed-out overlays them

    // epilogue: packed row per px: u32[0..15] qk fp32, u32[16..47] v bf16x2
    const float* sb = s1 + OFF_BIAS;
    #pragma unroll
    for (int mt = 0; mt < 2; mt++) {
        int p0 = pb + mt * 16 + grp;
        int p1 = p0 + 8;
        #pragma unroll
        for (int nt = 0; nt < 10; nt++) {
            int n0 = nt * 8 + 2 * tig;
            float b0v = sb[n0], b1v = sb[n0 + 1];
            float v00 = d[mt][nt][0] + b0v, v01 = d[mt][nt][1] + b1v;
            float v10 = d[mt][nt][2] + b0v, v11 = d[mt][nt][3] + b1v;
            if (nt < 2) {
                int wi = nt * 8 + 2 * tig;   // q: 0..7, k: 8..15
                *reinterpret_cast<float2*>(s1u + p0 * OSW_S + wi) = make_float2(v00, v01);
                *reinterpret_cast<float2*>(s1u + p1 * OSW_S + wi) = make_float2(v10, v11);
            } else {
                int wi = 16 + (nt - 2) * 4 + tig;
                s1u[p0 * OSW_S + wi] = bf16x2_rn(v00, v01);
                s1u[p1 * OSW_S + wi] = bf16x2_rn(v10, v11);
            }
        }
    }
    __syncthreads();

    // coalesced stream: 128 px * 12 uint4 (48 u32) contiguous
    uint4* dst = reinterpret_cast<uint4*>(g_qkv + ((size_t)b * HWPIX + hw0) * QKV_W);
    for (int i = tid; i < 1536; i += 128) {
        int p  = i / 12;
        int w4 = i - p * 12;
        dst[i] = *reinterpret_cast<const uint4*>(s1u + p * OSW_S + w4 * 4);
    }
}

// ===================== K2: attention — bf16 V in smem, 5 blocks/SM ============
// 128 threads = 4 warps; warp w owns rows [w*16,w*16+16) for BOTH windows.
// Pool/window (5392 floats): qkv[49][52 u32]@0 (2548) | att[49][58]@2548 (2842)
// os[49][66] (3234) overlays qkv+att after AV (both dead).
#define QKV_SU 52
#define AT_S   58
#define ATT_OFF 2548
#define OS_S   66
#define PW     5392
#define K2_SMEM_FLOATS (2*PW)               // 10784
#define K2_SMEM_BYTES  (K2_SMEM_FLOATS*4)   // 43136

__global__ void __launch_bounds__(128, 5)
attn_kernel(const float* __restrict__ x,
            const float* __restrict__ gamma,
            float* __restrict__ out)
{
    extern __shared__ float sp[];
    const int tid = threadIdx.x;
    const int blk = blockIdx.x;        // 16 b * 32 wh * 16 wpair
    const int b   = blk >> 9;
    const int rem = blk & 511;
    const int wh  = rem >> 4;
    const int wp  = rem & 15;
    const int h0  = wh * 7;
    const int w0  = wp * 14;

    const float g = __ldg(gamma);

    const int wid  = tid >> 5, lane = tid & 31;
    const int grp  = lane >> 2, tig = lane & 3;
    const int w16  = wid * 16;

    float* att0 = sp + ATT_OFF;
    float* att1 = sp + PW + ATT_OFF;
    u32* pu0 = reinterpret_cast<u32*>(sp);
    u32* pu1 = reinterpret_cast<u32*>(sp + PW);

    // ---- stage packed qkv: 98 px * 12 uint4, pure passthrough ----
    const u32* gq = g_qkv + ((size_t)b * HWPIX + (size_t)h0 * HWDIM + w0) * QKV_W;
    for (int i = tid; i < 1176; i += 128) {
        int ph = i / 168;
        int rr = i - ph * 168;
        int pw = rr / 12;
        int w4 = rr - pw * 12;
        int wn = (pw >= 7);
        int t  = ph * 7 + pw - 7 * wn;
        uint4 v = __ldg(reinterpret_cast<const uint4*>(gq + ((size_t)ph * HWDIM + pw) * QKV_W) + w4);
        *reinterpret_cast<uint4*>((wn ? pu1 : pu0) + t * QKV_SU + w4 * 4) = v;
    }
    __syncthreads();   // B1: staging visible

    // ---- QK^T: both windows interleaved; rows [w16, w16+16) ----
    {
        const int r0 = w16 + grp, r1 = r0 + 8;
        const int r0c = min(r0, 48), r1c = min(r1, 48);
        u32 aq0[4], aq1[4];
        aq0[0] = pu0[r0c * QKV_SU + tig];
        aq0[1] = pu0[r1c * QKV_SU + tig];
        aq0[2] = pu0[r0c * QKV_SU + tig + 4];
        aq0[3] = pu0[r1c * QKV_SU + tig + 4];
        aq1[0] = pu1[r0c * QKV_SU + tig];
        aq1[1] = pu1[r1c * QKV_SU + tig];
        aq1[2] = pu1[r0c * QKV_SU + tig + 4];
        aq1[3] = pu1[r1c * QKV_SU + tig + 4];

        float dq[2][7][4];
        #pragma unroll
        for (int wn = 0; wn < 2; wn++)
            #pragma unroll
            for (int nt = 0; nt < 7; nt++)
                #pragma unroll
                for (int e = 0; e < 4; e++) dq[wn][nt][e] = 0.0f;

        #pragma unroll
        for (int nt = 0; nt < 7; nt++) {
            int m = nt * 8 + grp;
            bool mv = (m < NTOK);
            u32 b00 = mv ? pu0[m * QKV_SU + 8 + tig]     : 0;
            u32 b01 = mv ? pu0[m * QKV_SU + 8 + tig + 4] : 0;
            u32 b10 = mv ? pu1[m * QKV_SU + 8 + tig]     : 0;
            u32 b11 = mv ? pu1[m * QKV_SU + 8 + tig + 4] : 0;
            mma_tf32(dq[0][nt], aq0, b00, b01);
            mma_tf32(dq[1][nt], aq1, b10, b11);
        }
        #pragma unroll
        for (int nt = 0; nt < 7; nt++) {
            int c0 = nt * 8 + 2 * tig;
            if (r0 < NTOK) {
                *reinterpret_cast<float2*>(att0 + r0 * AT_S + c0) = make_float2(dq[0][nt][0], dq[0][nt][1]);
                *reinterpret_cast<float2*>(att1 + r0 * AT_S + c0) = make_float2(dq[1][nt][0], dq[1][nt][1]);
            }
            if (r1 < NTOK) {
                *reinterpret_cast<float2*>(att0 + r1 * AT_S + c0) = make_float2(dq[0][nt][2], dq[0][nt][3]);
                *reinterpret_cast<float2*>(att1 + r1 * AT_S + c0) = make_float2(dq[1][nt][2], dq[1][nt][3]);
            }
        }
    }
    __syncwarp();

    // ---- softmax: lane<16 -> window0, lane>=16 -> window1 ----
    {
        int row = w16 + (lane & 15);
        float* ar = ((lane >> 4) ? att1 : att0) + row * AT_S;
        if (row < NTOK) {
            float mx = ar[0];
            #pragma unroll 7
            for (int m = 1; m < NTOK; m++) mx = fmaxf(mx, ar[m]);
            float s = 0.0f;
            #pragma unroll 7
            for (int m = 0; m < NTOK; m++) {
                float e = __expf(ar[m] - mx);
                ar[m] = e;
                s += e;
            }
            float rs = g / s;
            #pragma unroll 7
            for (int m = 0; m < NTOK; m++) ar[m] = tf32r(ar[m] * rs);
        }
    }
    __syncwarp();

    // ---- AV: V extracted bf16->tf32 in registers ----
    float dv[2][8][4];
    #pragma unroll
    for (int wn = 0; wn < 2; wn++)
        #pragma unroll
        for (int nt = 0; nt < 8; nt++)
            #pragma unroll
            for (int e = 0; e < 4; e++) dv[wn][nt][e] = 0.0f;
    {
        const u32* au0 = reinterpret_cast<const u32*>(att0);
        const u32* au1 = reinterpret_cast<const u32*>(att1);
        const int r0 = w16 + grp;
        const int r0c = min(r0, 48), r1c = min(r0 + 8, 48);
        const bool codd = (grp & 1);
        #pragma unroll
        for (int ks = 0; ks < 7; ks++) {
            int k0 = ks * 8;
            u32 a0[4], a1[4];
            a0[0] = au0[r0c * AT_S + k0 + tig];
            a0[1] = au0[r1c * AT_S + k0 + tig];
            a0[2] = au0[r0c * AT_S + k0 + tig + 4];
            a0[3] = au0[r1c * AT_S + k0 + tig + 4];
            a1[0] = au1[r0c * AT_S + k0 + tig];
            a1[1] = au1[r1c * AT_S + k0 + tig];
            a1[2] = au1[r0c * AT_S + k0 + tig + 4];
            a1[3] = au1[r1c * AT_S + k0 + tig + 4];
            int m0 = k0 + tig;
            #pragma unroll
            for (int nt = 0; nt < 8; nt++) {
                int vi = 16 + ((nt * 8 + grp) >> 1);
                u32 w00, w01, w10, w11;
                if (ks < 6) {
                    w00 = pu0[m0 * QKV_SU + vi];
                    w01 = pu0[(m0 + 4) * QKV_SU + vi];
                    w10 = pu1[m0 * QKV_SU + vi];
                    w11 = pu1[(m0 + 4) * QKV_SU + vi];
                } else {
                    bool mv = (m0 < NTOK);   // only m=48 real
                    w00 = mv ? pu0[m0 * QKV_SU + vi] : 0;
                    w10 = mv ? pu1[m0 * QKV_SU + vi] : 0;
                    w01 = 0; w11 = 0;
                }
                u32 b00 = codd ? (w00 & 0xffff0000u) : (w00 << 16);
                u32 b01 = codd ? (w01 & 0xffff0000u) : (w01 << 16);
                u32 b10 = codd ? (w10 & 0xffff0000u) : (w10 << 16);
                u32 b11 = codd ? (w11 & 0xffff0000u) : (w11 << 16);
                mma_tf32(dv[0][nt], a0, b00, b01);
                mma_tf32(dv[1][nt], a1, b10, b11);
            }
        }
    }
    __syncthreads();   // B2: all qkv/att reads done -> os overlays pool

    // ---- epilogue: os[t][66] over dead pool ----
    {
        const int r0 = w16 + grp, r1 = r0 + 8;
        #pragma unroll
        for (int nt = 0; nt < 8; nt++) {
            int c0 = nt * 8 + 2 * tig;
            if (r0 < NTOK) {
                *reinterpret_cast<float2*>(sp + r0 * OS_S + c0)      = make_float2(dv[0][nt][0], dv[0][nt][1]);
                *reinterpret_cast<float2*>(sp + PW + r0 * OS_S + c0) = make_float2(dv[1][nt][0], dv[1][nt][1]);
            }
            if (r1 < NTOK) {
                *reinterpret_cast<float2*>(sp + r1 * OS_S + c0)      = make_float2(dv[0][nt][2], dv[0][nt][3]);
                *reinterpret_cast<float2*>(sp + PW + r1 * OS_S + c0) = make_float2(dv[1][nt][2], dv[1][nt][3]);
            }
        }
    }
    __syncthreads();   // B3: os complete

    // ---- residual + store: 14-px contiguous lanes, 16-channel runs ----
    {
        const float* xb = x   + (size_t)b * CH * HWPIX;
        float*       ob = out + (size_t)b * CH * HWPIX;
        for (int u = tid; u < 392; u += 128) {
            int cr  = u / 98;
            int p14 = u - cr * 98;
            int ph  = p14 / 14;
            int pwx = p14 - ph * 14;
            int wn  = (pwx >= 7);
            int t   = ph * 7 + pwx - 7 * wn;
            const float* osr = sp + wn * PW + t * OS_S + cr * 16;
            size_t gi = (size_t)(cr * 16) * HWPIX + (size_t)(h0 + ph) * HWDIM + w0 + pwx;
            #pragma unroll
            for (int c = 0; c < 16; c++) {
                ob[gi] = osr[c] + __ldg(&xb[gi]);
                gi += HWPIX;
            }
        }
    }
}

extern "C" void kernel_launch(void* const* d_in, const int* in_sizes, int n_in,
                              void* d_out, int out_size)
{
    const float* x     = (const float*)d_in[0];
    const float* Wq    = (const float*)d_in[1];
    const float* bq    = (const float*)d_in[2];
    const float* Wk    = (const float*)d_in[3];
    const float* bk    = (const float*)d_in[4];
    const float* Wv    = (const float*)d_in[5];
    const float* bv    = (const float*)d_in[6];
    const float* gamma = (const float*)d_in[7];
    float* out = (float*)d_out;

    cudaFuncSetAttribute(proj_kernel, cudaFuncAttributeMaxDynamicSharedMemorySize, K1_SMEM_BYTES);
    cudaFuncSetAttribute(attn_kernel, cudaFuncAttributeMaxDynamicSharedMemorySize, K2_SMEM_BYTES);

    proj_kernel<<<NB * (HWPIX / 128), 128, K1_SMEM_BYTES>>>(x, Wq, bq, Wk, bk, Wv, bv);
    attn_kernel<<<NB * 32 * 16, 128, K2_SMEM_BYTES>>>(x, gamma, out);
}